// round 7
// baseline (speedup 1.0000x reference)
#include <cuda_runtime.h>

// Fixed shapes: n=2, c=64, s=4, h=64, w=44
#define N_  2
#define C_  64
#define S_  4
#define H_  64
#define W_  44
#define B_  (N_ * S_)            // 8 effective batches
#define P_  (H_ * W_)            // 2816 pixels
#define R_  3
#define KT  49

#define TH  4                    // tile rows per block
#define CC  8                    // channels staged per chunk
#define CP  (CC / 2)             // 4 channel-pairs per chunk
#define NCH (C_ / CC)            // 8 chunks
#define G_  4                    // threads (tap-groups) per pixel
#define NTAP 13                  // max taps per group
#define HALO_H (TH + 2 * R_)     // 10 shared rows
#define SW  52                   // 50 used cols + 2 pad
#define NTHREADS (W_ * TH * G_)  // 704

#define NF1 5                    // f1 scalar elems staged per thread per chunk
#define NF0 2                    // f0 scalar elems staged per thread per chunk
#define CHSTRIDE (S_ * P_)       // per-channel element stride

#define F1PLANE (HALO_H * SW)    // float2 elems per (pair) plane: 520
#define F0PLANE (TH * W_)        // float2 elems per (pair) plane: 176

__device__ __forceinline__ void ffma2(unsigned long long& d,
                                      unsigned long long a,
                                      unsigned long long b) {
    asm("fma.rn.f32x2 %0, %1, %2, %0;" : "+l"(d) : "l"(a), "l"(b));
}

__global__ __launch_bounds__(NTHREADS, 1)
void corr_flow_kernel(const float* __restrict__ f0g,
                      const float* __restrict__ f1g,
                      float* __restrict__ out) {
    // channel-pair interleaved: element = (ch_even, ch_odd)
    __shared__ float2 f1s[2][CP][HALO_H][SW];   // 2*4*10*52*8 = 33280 B
    __shared__ float2 f0s[2][CP][TH][W_];       // 2*4*4*44*8  = 11264 B

    const int tid = threadIdx.x;
    const int g   = tid & (G_ - 1);
    const int p   = tid >> 2;
    const int tx  = p % W_;
    const int ty  = p / W_;

    const int blk   = blockIdx.x;
    const int b     = blk >> 4;
    const int ytile = blk & 15;
    const int y0    = ytile * TH;
    const int n_idx = b / S_;
    const int s_idx = b - n_idx * S_;

    const int base = (n_idx * C_ * S_ + s_idx) * P_;

    // ---- precompute staging maps (chunk-invariant) ----
    // f1: scalar slot in interleaved float2 layout + global offset (or -1)
    int f1_s[NF1];
    int f1_g[NF1];
#pragma unroll
    for (int k = 0; k < NF1; k++) {
        int i   = tid + k * NTHREADS;
        int cc  = i / (HALO_H * W_);
        int rem = i - cc * (HALO_H * W_);
        int r   = rem / W_;
        int x   = rem - r * W_;
        int gy  = y0 - R_ + r;
        f1_s[k] = ((cc >> 1) * F1PLANE + r * SW + x + R_) * 2 + (cc & 1);
        f1_g[k] = (gy >= 0 && gy < H_) ? (base + cc * CHSTRIDE + gy * W_ + x) : -1;
    }
    int f0_s[NF0];
    int f0_g[NF0];
#pragma unroll
    for (int k = 0; k < NF0; k++) {
        int i   = tid + k * NTHREADS;
        int cc  = i / (TH * W_);
        int rem = i - cc * (TH * W_);
        int r   = rem / W_;
        int x   = rem - r * W_;
        f0_s[k] = ((cc >> 1) * F0PLANE + rem) * 2 + (cc & 1);
        f0_g[k] = base + cc * CHSTRIDE + (y0 + r) * W_ + x;
    }

    // per-thread tap offsets (float2 units) in a f1 plane: tap t = g + 4*i
    int off[NTAP];
#pragma unroll
    for (int i = 0; i < NTAP; i++) {
        int t = g + G_ * i;
        if (t > 48) t = 48;
        off[i] = (t / 7) * SW + (t % 7);
    }
    unsigned long long acc2[NTAP];
#pragma unroll
    for (int i = 0; i < NTAP; i++) acc2[i] = 0ull;

    // zero both f1 buffers once (halo cols / out-of-image rows stay zero)
    {
        float* zp = (float*)&f1s[0][0][0][0];
        for (int i = tid; i < 2 * CP * F1PLANE * 2; i += NTHREADS) zp[i] = 0.f;
    }

    const int last = (g == 0) ? NTAP : (NTAP - 1);

    // ---- prologue: prefetch chunk 0 into buffer 0 ----
    float r1[NF1], r0[NF0];
#pragma unroll
    for (int k = 0; k < NF1; k++) r1[k] = (f1_g[k] >= 0) ? f1g[f1_g[k]] : 0.f;
#pragma unroll
    for (int k = 0; k < NF0; k++) r0[k] = f0g[f0_g[k]];

    float* f1b0 = (float*)&f1s[0][0][0][0];
    float* f1b1 = (float*)&f1s[1][0][0][0];
    float* f0b0 = (float*)&f0s[0][0][0][0];
    float* f0b1 = (float*)&f0s[1][0][0][0];

#pragma unroll
    for (int k = 0; k < NF1; k++) f1b0[f1_s[k]] = r1[k];
#pragma unroll
    for (int k = 0; k < NF0; k++) f0b0[f0_s[k]] = r0[k];
    __syncthreads();

    // ---- pipelined mainloop ----
#pragma unroll 2
    for (int c = 0; c < NCH; c++) {
        if (c < NCH - 1) {
            int ch_off = (c + 1) * CC * CHSTRIDE;
#pragma unroll
            for (int k = 0; k < NF1; k++)
                r1[k] = (f1_g[k] >= 0) ? f1g[f1_g[k] + ch_off] : 0.f;
#pragma unroll
            for (int k = 0; k < NF0; k++)
                r0[k] = f0g[f0_g[k] + ch_off];
        }

        const unsigned long long* f1p =
            (const unsigned long long*)((c & 1) ? f1b1 : f1b0) + ty * SW + tx;
        const unsigned long long* f0p =
            (const unsigned long long*)((c & 1) ? f0b1 : f0b0) + ty * W_ + tx;

#pragma unroll
        for (int cp = 0; cp < CP; cp++) {
            unsigned long long a2 = f0p[cp * F0PLANE];   // broadcast over 4 lanes
            const unsigned long long* fp = f1p + cp * F1PLANE;
#pragma unroll
            for (int i = 0; i < NTAP; i++) {
                if (i < last) ffma2(acc2[i], a2, fp[off[i]]);
            }
        }

        if (c < NCH - 1) {
            float* f1d = (c & 1) ? f1b0 : f1b1;
            float* f0d = (c & 1) ? f0b0 : f0b1;
#pragma unroll
            for (int k = 0; k < NF1; k++) f1d[f1_s[k]] = r1[k];
#pragma unroll
            for (int k = 0; k < NF0; k++) f0d[f0_s[k]] = r0[k];
            __syncthreads();
        }
    }

    // collapse channel pairs: acc = lo + hi
    float acc[NTAP];
#pragma unroll
    for (int i = 0; i < NTAP; i++) {
        float2 v = *reinterpret_cast<float2*>(&acc2[i]);
        acc[i] = v.x + v.y;
    }

    // ---- epilogue: masked softmax over taps, split across 4 lanes ----
    const int x = tx;
    const int y = y0 + ty;
    const float scale = 0.125f;

    float m = -1e30f;
#pragma unroll
    for (int i = 0; i < NTAP; i++) {
        int t = g + G_ * i;
        if (t < KT) {
            int dx = t % 7 - R_;
            int dy = t / 7 - R_;
            int gx = x + dx, gy = y + dy;
            if (gx >= 0 && gx < W_ && gy >= 0 && gy < H_)
                m = fmaxf(m, acc[i] * scale);
        }
    }
    m = fmaxf(m, __shfl_xor_sync(0xffffffffu, m, 1));
    m = fmaxf(m, __shfl_xor_sync(0xffffffffu, m, 2));

    float se = 0.f, sx = 0.f, sy = 0.f;
#pragma unroll
    for (int i = 0; i < NTAP; i++) {
        int t = g + G_ * i;
        if (t < KT) {
            int dx = t % 7 - R_;
            int dy = t / 7 - R_;
            int gx = x + dx, gy = y + dy;
            if (gx >= 0 && gx < W_ && gy >= 0 && gy < H_) {
                float e = __expf(acc[i] * scale - m);
                se += e;
                sx += e * (float)dx;
                sy += e * (float)dy;
            }
        }
    }
    se += __shfl_xor_sync(0xffffffffu, se, 1);
    se += __shfl_xor_sync(0xffffffffu, se, 2);
    sx += __shfl_xor_sync(0xffffffffu, sx, 1);
    sx += __shfl_xor_sync(0xffffffffu, sx, 2);
    sy += __shfl_xor_sync(0xffffffffu, sy, 1);
    sy += __shfl_xor_sync(0xffffffffu, sy, 2);

    if (g == 0) {
        float inv = 1.0f / se;
        int ob = ((n_idx * 2) * S_ + s_idx) * P_ + y * W_ + x;
        out[ob]           = sx * inv;
        out[ob + S_ * P_] = sy * inv;
    }
}

extern "C" void kernel_launch(void* const* d_in, const int* in_sizes, int n_in,
                              void* d_out, int out_size) {
    const float* f0 = (const float*)d_in[0];
    const float* f1 = (const float*)d_in[1];
    float* out = (float*)d_out;
    corr_flow_kernel<<<B_ * (H_ / TH), NTHREADS>>>(f0, f1, out);
}